// round 3
// baseline (speedup 1.0000x reference)
#include <cuda_runtime.h>

// Problem constants (fixed shapes per reference)
#define NNODES 50000
#define NEDGES 800000
#define ETOT   (NNODES + NEDGES)   // edges + self loops
#define FIN    256
#define HIDTOT 256                 // HEADS*HID
#define NHEADS 4
#define NCLS   32

typedef unsigned long long ull;

#define FMA2(d, a, b) asm("fma.rn.f32x2 %0, %1, %2, %3;" : "=l"(d) : "l"(a), "l"(b), "l"(d))

// ---------------- scratch (device globals; no allocation allowed) ----------
__device__ int   g_src[ETOT];
__device__ int   g_dst[ETOT];
__device__ int   g_csr[ETOT];
__device__ int   g_count[NNODES];
__device__ int   g_cursor[NNODES];
__device__ int   g_off[NNODES + 1];
__device__ int   g_bsum[64];
__device__ int   g_boff[64];
__device__ float g_h1[(size_t)NNODES * HIDTOT];
__device__ float g_als1[NNODES * NHEADS];
__device__ float g_ald1[NNODES * NHEADS];
__device__ float g_h2in[(size_t)NNODES * HIDTOT];
__device__ float g_h2[(size_t)NNODES * NCLS];
__device__ float g_als2[NNODES];
__device__ float g_ald2[NNODES];

// ---------------- CSR construction ----------------------------------------
__global__ void k_zero(int n) {
    int i = blockIdx.x * blockDim.x + threadIdx.x;
    if (i < n) { g_count[i] = 0; g_cursor[i] = 0; }
}

__global__ void k_convert(const void* __restrict__ edges, int E, int n) {
    __shared__ int s_is64;
    if (threadIdx.x == 0) {
        const long long* q = (const long long*)edges;
        int ok = 1;
#pragma unroll
        for (int t = 0; t < 16; t++) {
            long long v = q[t];
            if (v < 0 || v >= (long long)n) ok = 0;
        }
        s_is64 = ok;
    }
    __syncthreads();
    int i = blockIdx.x * blockDim.x + threadIdx.x;
    int Et = E + n;
    if (i >= Et) return;
    int s, d;
    if (i < E) {
        if (s_is64) {
            const long long* q = (const long long*)edges;
            s = (int)q[i];
            d = (int)q[(long long)E + i];
        } else {
            const int* q = (const int*)edges;
            s = q[i];
            d = q[E + i];
        }
    } else {
        s = i - E; d = i - E;   // self loop
    }
    g_src[i] = s;
    g_dst[i] = d;
    atomicAdd(&g_count[d], 1);
}

__global__ void k_scan_local(int n) {
    __shared__ int sh[1024];
    int i = blockIdx.x * 1024 + threadIdx.x;
    int v = (i < n) ? g_count[i] : 0;
    sh[threadIdx.x] = v;
    __syncthreads();
    for (int off = 1; off < 1024; off <<= 1) {
        int t = (threadIdx.x >= off) ? sh[threadIdx.x - off] : 0;
        __syncthreads();
        sh[threadIdx.x] += t;
        __syncthreads();
    }
    if (i < n) g_off[i] = sh[threadIdx.x] - v;           // exclusive
    if (threadIdx.x == 1023) g_bsum[blockIdx.x] = sh[1023];
}

__global__ void k_scan_sums(int nb) {
    __shared__ int sh[64];
    int v = (threadIdx.x < nb) ? g_bsum[threadIdx.x] : 0;
    sh[threadIdx.x] = v;
    __syncthreads();
    for (int off = 1; off < 64; off <<= 1) {
        int t = (threadIdx.x >= off) ? sh[threadIdx.x - off] : 0;
        __syncthreads();
        sh[threadIdx.x] += t;
        __syncthreads();
    }
    g_boff[threadIdx.x] = sh[threadIdx.x] - v;
}

__global__ void k_scan_add(int n, int Et) {
    int i = blockIdx.x * 1024 + threadIdx.x;
    if (i < n) g_off[i] += g_boff[blockIdx.x];
    if (i == 0) g_off[n] = Et;
}

__global__ void k_scatter(int Et) {
    int i = blockIdx.x * blockDim.x + threadIdx.x;
    if (i >= Et) return;
    int d = g_dst[i];
    int pos = g_off[d] + atomicAdd(&g_cursor[d], 1);
    g_csr[pos] = g_src[i];
}

// ---------------- GEMM1: h1 = x @ W1 (M x 256 x 256), FFMA2, fused al1 -----
// 128x64 tile, TK=16, 256 threads. Row-pairs packed into f32x2; B duplicated
// in smem so the (b,b) operand is a direct LDS.128. Col-block == one head,
// so the a_src/a_dst dots reduce fully inside the block (no extra kernel).
__global__ void k_gemm1(const float* __restrict__ X, const float* __restrict__ W,
                        const float* __restrict__ a_src, const float* __restrict__ a_dst,
                        int M) {
    const int K = FIN, N = HIDTOT;
    __shared__ float As[16][132];        // [k][m], 528B rows (16B aligned)
    __shared__ float Bs[16][132];        // [k][2*col] duplicated, 128 used
    int tid = threadIdx.x;
    int row0 = blockIdx.y * 128;
    int col0 = blockIdx.x * 64;
    int tn = tid & 15, tm = tid >> 4;

    ull acc[4][4];                        // [row-pair][col], f32x2 packed
#pragma unroll
    for (int jp = 0; jp < 4; jp++)
#pragma unroll
        for (int c = 0; c < 4; c++) acc[jp][c] = 0ull;

    const float4* X4 = (const float4*)X;
    const float4* W4 = (const float4*)W;

    for (int k0 = 0; k0 < K; k0 += 16) {
        // A tile: 128 rows x 16 k
#pragma unroll
        for (int r = 0; r < 2; r++) {
            int f = tid + r * 256;
            int m = f >> 2, kq = f & 3;
            int row = row0 + m;
            float4 v = make_float4(0.f, 0.f, 0.f, 0.f);
            if (row < M) v = X4[(size_t)row * (K / 4) + (k0 >> 2) + kq];
            As[kq * 4 + 0][m] = v.x;
            As[kq * 4 + 1][m] = v.y;
            As[kq * 4 + 2][m] = v.z;
            As[kq * 4 + 3][m] = v.w;
        }
        // B tile duplicated: 16 k x 64 n -> 128 floats per k-row
        {
            int k = tid >> 4, nq = tid & 15;
            float4 v = W4[(size_t)(k0 + k) * (N / 4) + (col0 >> 2) + nq];
            Bs[k][8 * nq + 0] = v.x; Bs[k][8 * nq + 1] = v.x;
            Bs[k][8 * nq + 2] = v.y; Bs[k][8 * nq + 3] = v.y;
            Bs[k][8 * nq + 4] = v.z; Bs[k][8 * nq + 5] = v.z;
            Bs[k][8 * nq + 6] = v.w; Bs[k][8 * nq + 7] = v.w;
        }
        __syncthreads();
#pragma unroll
        for (int k = 0; k < 16; k++) {
            ulonglong2 a0 = *(const ulonglong2*)&As[k][tm * 8];
            ulonglong2 a1 = *(const ulonglong2*)&As[k][tm * 8 + 4];
            ulonglong2 b0 = *(const ulonglong2*)&Bs[k][8 * tn];
            ulonglong2 b1 = *(const ulonglong2*)&Bs[k][8 * tn + 4];
            ull ap[4] = {a0.x, a0.y, a1.x, a1.y};
            ull bd[4] = {b0.x, b0.y, b1.x, b1.y};
#pragma unroll
            for (int jp = 0; jp < 4; jp++) {
                FMA2(acc[jp][0], ap[jp], bd[0]);
                FMA2(acc[jp][1], ap[jp], bd[1]);
                FMA2(acc[jp][2], ap[jp], bd[2]);
                FMA2(acc[jp][3], ap[jp], bd[3]);
            }
        }
        __syncthreads();
    }

    // epilogue: store h1 rows + fused attention-logit dots for this head
    int h = blockIdx.x;                  // col-block == head
    float4 asv = ((const float4*)(a_src + (h << 6)))[tn];
    float4 adv = ((const float4*)(a_dst + (h << 6)))[tn];
#pragma unroll
    for (int jp = 0; jp < 4; jp++) {
#pragma unroll
        for (int p = 0; p < 2; p++) {
            int row = row0 + tm * 8 + jp * 2 + p;
            float v0 = ((const float2*)&acc[jp][0])[0].x, v0b;
            float2 c0 = *(const float2*)&acc[jp][0];
            float2 c1 = *(const float2*)&acc[jp][1];
            float2 c2 = *(const float2*)&acc[jp][2];
            float2 c3 = *(const float2*)&acc[jp][3];
            float w0 = p ? c0.y : c0.x;
            float w1 = p ? c1.y : c1.x;
            float w2 = p ? c2.y : c2.x;
            float w3 = p ? c3.y : c3.x;
            (void)v0; (void)v0b;
            float ps = w0 * asv.x + w1 * asv.y + w2 * asv.z + w3 * asv.w;
            float pd = w0 * adv.x + w1 * adv.y + w2 * adv.z + w3 * adv.w;
#pragma unroll
            for (int o = 8; o >= 1; o >>= 1) {
                ps += __shfl_xor_sync(0xffffffffu, ps, o);
                pd += __shfl_xor_sync(0xffffffffu, pd, o);
            }
            if (row < M) {
                ((float4*)g_h1)[(size_t)row * (HIDTOT / 4) + (col0 >> 2) + tn] =
                    make_float4(w0, w1, w2, w3);
                if (tn == 0) {
                    g_als1[row * NHEADS + h] = ps;
                    g_ald1[row * NHEADS + h] = pd;
                }
            }
        }
    }
}

// ---------------- layer-1 aggregation: softmax (no max shift), warp/node ---
__global__ void k_agg1(const float* __restrict__ b1, int M) {
    int w = (blockIdx.x * blockDim.x + threadIdx.x) >> 5;
    int lane = threadIdx.x & 31;
    if (w >= M) return;
    int h = lane >> 3;
    float ald = g_ald1[w * NHEADS + h];
    int beg = g_off[w], end = g_off[w + 1];
    float s = 0.f;
    float acc[8];
#pragma unroll
    for (int j = 0; j < 8; j++) acc[j] = 0.f;

#pragma unroll 2
    for (int idx = beg; idx < end; ++idx) {
        int src = g_csr[idx];
        float e = g_als1[src * NHEADS + h] + ald;
        e = (e > 0.f) ? e : 0.2f * e;
        float p = __expf(e);
        const float4* hp = (const float4*)(g_h1 + (size_t)src * HIDTOT);
        float4 v0 = hp[lane * 2], v1 = hp[lane * 2 + 1];
        s += p;
        acc[0] += p * v0.x; acc[1] += p * v0.y;
        acc[2] += p * v0.z; acc[3] += p * v0.w;
        acc[4] += p * v1.x; acc[5] += p * v1.y;
        acc[6] += p * v1.z; acc[7] += p * v1.w;
    }
    float inv = 1.f / s;
#pragma unroll
    for (int j = 0; j < 8; j++) {
        float v = acc[j] * inv + b1[lane * 8 + j];
        v = (v > 0.f) ? v : (__expf(v) - 1.f);          // ELU
        g_h2in[(size_t)w * HIDTOT + lane * 8 + j] = v;
    }
}

// ---------------- GEMM2: h2 = h2in @ W2 (M x 256 x 32), FFMA2, fused al2 ---
__global__ void k_gemm2(const float* __restrict__ W2,
                        const float* __restrict__ a_src, const float* __restrict__ a_dst,
                        int M) {
    const int K = HIDTOT, N = NCLS;
    __shared__ float As[16][132];
    __shared__ float Bs[16][68];          // duplicated, 64 used; 272B rows
    int tid = threadIdx.x;
    int row0 = blockIdx.x * 128;
    int tn = tid & 15, tm = tid >> 4;

    ull acc[4][2];
#pragma unroll
    for (int jp = 0; jp < 4; jp++) { acc[jp][0] = 0ull; acc[jp][1] = 0ull; }

    const float4* A4 = (const float4*)g_h2in;
    const float4* W4 = (const float4*)W2;

    for (int k0 = 0; k0 < K; k0 += 16) {
#pragma unroll
        for (int r = 0; r < 2; r++) {
            int f = tid + r * 256;
            int m = f >> 2, kq = f & 3;
            int row = row0 + m;
            float4 v = make_float4(0.f, 0.f, 0.f, 0.f);
            if (row < M) v = A4[(size_t)row * (K / 4) + (k0 >> 2) + kq];
            As[kq * 4 + 0][m] = v.x;
            As[kq * 4 + 1][m] = v.y;
            As[kq * 4 + 2][m] = v.z;
            As[kq * 4 + 3][m] = v.w;
        }
        if (tid < 128) {
            int k = tid >> 3, nq = tid & 7;
            float4 v = W4[(size_t)(k0 + k) * (N / 4) + nq];
            Bs[k][8 * nq + 0] = v.x; Bs[k][8 * nq + 1] = v.x;
            Bs[k][8 * nq + 2] = v.y; Bs[k][8 * nq + 3] = v.y;
            Bs[k][8 * nq + 4] = v.z; Bs[k][8 * nq + 5] = v.z;
            Bs[k][8 * nq + 6] = v.w; Bs[k][8 * nq + 7] = v.w;
        }
        __syncthreads();
#pragma unroll
        for (int k = 0; k < 16; k++) {
            ulonglong2 a0 = *(const ulonglong2*)&As[k][tm * 8];
            ulonglong2 a1 = *(const ulonglong2*)&As[k][tm * 8 + 4];
            ulonglong2 bb = *(const ulonglong2*)&Bs[k][4 * tn];
            ull ap[4] = {a0.x, a0.y, a1.x, a1.y};
#pragma unroll
            for (int jp = 0; jp < 4; jp++) {
                FMA2(acc[jp][0], ap[jp], bb.x);
                FMA2(acc[jp][1], ap[jp], bb.y);
            }
        }
        __syncthreads();
    }

    float s0 = a_src[2 * tn], s1 = a_src[2 * tn + 1];
    float d0 = a_dst[2 * tn], d1 = a_dst[2 * tn + 1];
#pragma unroll
    for (int jp = 0; jp < 4; jp++) {
#pragma unroll
        for (int p = 0; p < 2; p++) {
            int row = row0 + tm * 8 + jp * 2 + p;
            float2 c0 = *(const float2*)&acc[jp][0];
            float2 c1 = *(const float2*)&acc[jp][1];
            float w0 = p ? c0.y : c0.x;
            float w1 = p ? c1.y : c1.x;
            float ps = w0 * s0 + w1 * s1;
            float pd = w0 * d0 + w1 * d1;
#pragma unroll
            for (int o = 8; o >= 1; o >>= 1) {
                ps += __shfl_xor_sync(0xffffffffu, ps, o);
                pd += __shfl_xor_sync(0xffffffffu, pd, o);
            }
            if (row < M) {
                ((float2*)g_h2)[(size_t)row * (NCLS / 2) + tn] = make_float2(w0, w1);
                if (tn == 0) { g_als2[row] = ps; g_ald2[row] = pd; }
            }
        }
    }
}

// ---------------- layer-2 aggregation + log_softmax, warp per node ---------
__global__ void k_agg2(const float* __restrict__ b2, float* __restrict__ out, int M) {
    int w = (blockIdx.x * blockDim.x + threadIdx.x) >> 5;
    int lane = threadIdx.x & 31;
    if (w >= M) return;
    float ald = g_ald2[w];
    int beg = g_off[w], end = g_off[w + 1];
    float s = 0.f, acc = 0.f;
#pragma unroll 2
    for (int idx = beg; idx < end; ++idx) {
        int src = g_csr[idx];
        float e = g_als2[src] + ald;
        e = (e > 0.f) ? e : 0.2f * e;
        float p = __expf(e);
        float hv = g_h2[(size_t)src * NCLS + lane];
        s += p;
        acc += p * hv;
    }
    float v = acc / s + b2[lane];
    float mx = v;
#pragma unroll
    for (int o = 16; o >= 1; o >>= 1) mx = fmaxf(mx, __shfl_xor_sync(0xffffffffu, mx, o));
    float ex = __expf(v - mx);
    float sum = ex;
#pragma unroll
    for (int o = 16; o >= 1; o >>= 1) sum += __shfl_xor_sync(0xffffffffu, sum, o);
    out[(size_t)w * NCLS + lane] = v - mx - logf(sum);
}

// ---------------- launch ----------------------------------------------------
extern "C" void kernel_launch(void* const* d_in, const int* in_sizes, int n_in,
                              void* d_out, int out_size) {
    const float* x   = (const float*)d_in[0];
    const void*  ei  = d_in[1];
    const float* W1  = (const float*)d_in[2];
    const float* as1 = (const float*)d_in[3];
    const float* ad1 = (const float*)d_in[4];
    const float* b1  = (const float*)d_in[5];
    const float* W2  = (const float*)d_in[6];
    const float* as2 = (const float*)d_in[7];
    const float* ad2 = (const float*)d_in[8];
    const float* b2  = (const float*)d_in[9];
    float* out = (float*)d_out;

    int M  = in_sizes[0] / FIN;       // 50000
    int E  = in_sizes[1] / 2;         // 800000
    int Et = E + M;

    // GEMM1 first: independent of the CSR chain
    dim3 g1(HIDTOT / 64, (M + 127) / 128);
    k_gemm1<<<g1, 256>>>(x, W1, as1, ad1, M);

    // CSR by destination
    k_zero<<<(M + 255) / 256, 256>>>(M);
    k_convert<<<(Et + 255) / 256, 256>>>(ei, E, M);
    int nb = (M + 1023) / 1024;
    k_scan_local<<<nb, 1024>>>(M);
    k_scan_sums<<<1, 64>>>(nb);
    k_scan_add<<<nb, 1024>>>(M, Et);
    k_scatter<<<(Et + 255) / 256, 256>>>(Et);

    // Layer 1 aggregate, layer 2
    k_agg1<<<(M + 7) / 8, 256>>>(b1, M);
    k_gemm2<<<(M + 127) / 128, 256>>>(W2, as2, ad2, M);
    k_agg2<<<(M + 7) / 8, 256>>>(b2, out, M);
}

// round 5
// speedup vs baseline: 1.4475x; 1.4475x over previous
#include <cuda_runtime.h>

// Problem constants (fixed shapes per reference)
#define NNODES 50000
#define NEDGES 800000
#define ETOT   (NNODES + NEDGES)   // edges + self loops
#define FIN    256
#define HIDTOT 256                 // HEADS*HID
#define NHEADS 4
#define NCLS   32

typedef unsigned long long ull;

// read-modify-write accumulator: d = a*b + d (packed f32x2)
#define FMA2(d, a, b) asm("fma.rn.f32x2 %0, %1, %2, %0;" : "+l"(d) : "l"(a), "l"(b))
// pack one float into both halves of a 64-bit register
#define DUP2(d, s)    asm("mov.b64 %0, {%1, %1};" : "=l"(d) : "f"(s))

// ---------------- scratch (device globals; no allocation allowed) ----------
__device__ int   g_src[ETOT];
__device__ int   g_dst[ETOT];
__device__ int   g_csr[ETOT];
__device__ int   g_count[NNODES];
__device__ int   g_cursor[NNODES];
__device__ int   g_off[NNODES + 1];
__device__ int   g_bsum[64];
__device__ int   g_boff[64];
__device__ float g_h1[(size_t)NNODES * HIDTOT];
__device__ float g_als1[NNODES * NHEADS];
__device__ float g_ald1[NNODES * NHEADS];
__device__ float g_h2in[(size_t)NNODES * HIDTOT];
__device__ float g_h2[(size_t)NNODES * NCLS];
__device__ float g_als2[NNODES];
__device__ float g_ald2[NNODES];

// ---------------- CSR construction ----------------------------------------
__global__ void k_zero(int n) {
    int i = blockIdx.x * blockDim.x + threadIdx.x;
    if (i < n) { g_count[i] = 0; g_cursor[i] = 0; }
}

__global__ void k_convert(const void* __restrict__ edges, int E, int n) {
    __shared__ int s_is64;
    if (threadIdx.x == 0) {
        const long long* q = (const long long*)edges;
        int ok = 1;
#pragma unroll
        for (int t = 0; t < 16; t++) {
            long long v = q[t];
            if (v < 0 || v >= (long long)n) ok = 0;
        }
        s_is64 = ok;
    }
    __syncthreads();
    int i = blockIdx.x * blockDim.x + threadIdx.x;
    int Et = E + n;
    if (i >= Et) return;
    int s, d;
    if (i < E) {
        if (s_is64) {
            const long long* q = (const long long*)edges;
            s = (int)q[i];
            d = (int)q[(long long)E + i];
        } else {
            const int* q = (const int*)edges;
            s = q[i];
            d = q[E + i];
        }
    } else {
        s = i - E; d = i - E;   // self loop
    }
    g_src[i] = s;
    g_dst[i] = d;
    atomicAdd(&g_count[d], 1);
}

__global__ void k_scan_local(int n) {
    __shared__ int sh[1024];
    int i = blockIdx.x * 1024 + threadIdx.x;
    int v = (i < n) ? g_count[i] : 0;
    sh[threadIdx.x] = v;
    __syncthreads();
    for (int off = 1; off < 1024; off <<= 1) {
        int t = (threadIdx.x >= off) ? sh[threadIdx.x - off] : 0;
        __syncthreads();
        sh[threadIdx.x] += t;
        __syncthreads();
    }
    if (i < n) g_off[i] = sh[threadIdx.x] - v;           // exclusive
    if (threadIdx.x == 1023) g_bsum[blockIdx.x] = sh[1023];
}

__global__ void k_scan_sums(int nb) {
    __shared__ int sh[64];
    int v = (threadIdx.x < nb) ? g_bsum[threadIdx.x] : 0;
    sh[threadIdx.x] = v;
    __syncthreads();
    for (int off = 1; off < 64; off <<= 1) {
        int t = (threadIdx.x >= off) ? sh[threadIdx.x - off] : 0;
        __syncthreads();
        sh[threadIdx.x] += t;
        __syncthreads();
    }
    g_boff[threadIdx.x] = sh[threadIdx.x] - v;
}

__global__ void k_scan_add(int n, int Et) {
    int i = blockIdx.x * 1024 + threadIdx.x;
    if (i < n) g_off[i] += g_boff[blockIdx.x];
    if (i == 0) g_off[n] = Et;
}

__global__ void k_scatter(int Et) {
    int i = blockIdx.x * blockDim.x + threadIdx.x;
    if (i >= Et) return;
    int d = g_dst[i];
    int pos = g_off[d] + atomicAdd(&g_cursor[d], 1);
    g_csr[pos] = g_src[i];
}

// ---------------- GEMM1: h1 = x @ W1 (M x 256 x 256), FFMA2, fused al1 -----
// 128x64 tile, TK=16, 256 threads. Row pairs packed into f32x2 (natural
// 64-bit LDS from the [k][m] A tile); B compact float4, dup'd into registers
// with mov.b64. Col-block == one head, so the a_src/a_dst dots reduce fully
// inside the block epilogue.
__global__ void k_gemm1(const float* __restrict__ X, const float* __restrict__ W,
                        const float* __restrict__ a_src, const float* __restrict__ a_dst,
                        int M) {
    const int K = FIN, N = HIDTOT;
    __shared__ float  As[16][132];       // [k][m]
    __shared__ float4 Bs[16][16];        // [k][n/4]
    int tid = threadIdx.x;
    int row0 = blockIdx.y * 128;
    int col0 = blockIdx.x * 64;
    int tn = tid & 15, tm = tid >> 4;

    ull acc[4][4];                        // [row-pair][col]
#pragma unroll
    for (int jp = 0; jp < 4; jp++)
#pragma unroll
        for (int c = 0; c < 4; c++) acc[jp][c] = 0ull;

    const float4* X4 = (const float4*)X;
    const float4* W4 = (const float4*)W;

    for (int k0 = 0; k0 < K; k0 += 16) {
#pragma unroll
        for (int r = 0; r < 2; r++) {
            int f = tid + r * 256;
            int m = f >> 2, kq = f & 3;
            int row = row0 + m;
            float4 v = make_float4(0.f, 0.f, 0.f, 0.f);
            if (row < M) v = X4[(size_t)row * (K / 4) + (k0 >> 2) + kq];
            As[kq * 4 + 0][m] = v.x;
            As[kq * 4 + 1][m] = v.y;
            As[kq * 4 + 2][m] = v.z;
            As[kq * 4 + 3][m] = v.w;
        }
        {
            int k = tid >> 4, nq = tid & 15;
            Bs[k][nq] = W4[(size_t)(k0 + k) * (N / 4) + (col0 >> 2) + nq];
        }
        __syncthreads();
#pragma unroll
        for (int k = 0; k < 16; k++) {
            ulonglong2 a0 = *(const ulonglong2*)&As[k][tm * 8];
            ulonglong2 a1 = *(const ulonglong2*)&As[k][tm * 8 + 4];
            float4 b = Bs[k][tn];
            ull bx, by, bz, bw;
            DUP2(bx, b.x); DUP2(by, b.y); DUP2(bz, b.z); DUP2(bw, b.w);
            ull ap[4] = {a0.x, a0.y, a1.x, a1.y};
#pragma unroll
            for (int jp = 0; jp < 4; jp++) {
                FMA2(acc[jp][0], ap[jp], bx);
                FMA2(acc[jp][1], ap[jp], by);
                FMA2(acc[jp][2], ap[jp], bz);
                FMA2(acc[jp][3], ap[jp], bw);
            }
        }
        __syncthreads();
    }

    // epilogue: store h1 rows + fused attention-logit dots for this head
    int h = blockIdx.x;                  // col-block == head
    float4 asv = ((const float4*)(a_src + (h << 6)))[tn];
    float4 adv = ((const float4*)(a_dst + (h << 6)))[tn];
#pragma unroll
    for (int jp = 0; jp < 4; jp++) {
#pragma unroll
        for (int p = 0; p < 2; p++) {
            int row = row0 + tm * 8 + jp * 2 + p;
            float2 c0 = *(const float2*)&acc[jp][0];
            float2 c1 = *(const float2*)&acc[jp][1];
            float2 c2 = *(const float2*)&acc[jp][2];
            float2 c3 = *(const float2*)&acc[jp][3];
            float w0 = p ? c0.y : c0.x;
            float w1 = p ? c1.y : c1.x;
            float w2 = p ? c2.y : c2.x;
            float w3 = p ? c3.y : c3.x;
            float ps = w0 * asv.x + w1 * asv.y + w2 * asv.z + w3 * asv.w;
            float pd = w0 * adv.x + w1 * adv.y + w2 * adv.z + w3 * adv.w;
#pragma unroll
            for (int o = 8; o >= 1; o >>= 1) {
                ps += __shfl_xor_sync(0xffffffffu, ps, o);
                pd += __shfl_xor_sync(0xffffffffu, pd, o);
            }
            if (row < M) {
                ((float4*)g_h1)[(size_t)row * (HIDTOT / 4) + (col0 >> 2) + tn] =
                    make_float4(w0, w1, w2, w3);
                if (tn == 0) {
                    g_als1[row * NHEADS + h] = ps;
                    g_ald1[row * NHEADS + h] = pd;
                }
            }
        }
    }
}

// ---------------- layer-1 aggregation: softmax (no max shift), warp/node ---
__global__ void k_agg1(const float* __restrict__ b1, int M) {
    int w = (blockIdx.x * blockDim.x + threadIdx.x) >> 5;
    int lane = threadIdx.x & 31;
    if (w >= M) return;
    int h = lane >> 3;
    float ald = g_ald1[w * NHEADS + h];
    int beg = g_off[w], end = g_off[w + 1];
    float s = 0.f;
    float acc[8];
#pragma unroll
    for (int j = 0; j < 8; j++) acc[j] = 0.f;

#pragma unroll 2
    for (int idx = beg; idx < end; ++idx) {
        int src = g_csr[idx];
        float e = g_als1[src * NHEADS + h] + ald;
        e = (e > 0.f) ? e : 0.2f * e;
        float p = __expf(e);
        const float4* hp = (const float4*)(g_h1 + (size_t)src * HIDTOT);
        float4 v0 = hp[lane * 2], v1 = hp[lane * 2 + 1];
        s += p;
        acc[0] += p * v0.x; acc[1] += p * v0.y;
        acc[2] += p * v0.z; acc[3] += p * v0.w;
        acc[4] += p * v1.x; acc[5] += p * v1.y;
        acc[6] += p * v1.z; acc[7] += p * v1.w;
    }
    float inv = 1.f / s;
#pragma unroll
    for (int j = 0; j < 8; j++) {
        float v = acc[j] * inv + b1[lane * 8 + j];
        v = (v > 0.f) ? v : (__expf(v) - 1.f);          // ELU
        g_h2in[(size_t)w * HIDTOT + lane * 8 + j] = v;
    }
}

// ---------------- GEMM2: h2 = h2in @ W2 (M x 256 x 32), FFMA2, fused al2 ---
__global__ void k_gemm2(const float* __restrict__ W2,
                        const float* __restrict__ a_src, const float* __restrict__ a_dst,
                        int M) {
    const int K = HIDTOT, N = NCLS;
    __shared__ float As[16][132];
    __shared__ float Bs[16][36];          // compact 32 + pad (16B-aligned rows)
    int tid = threadIdx.x;
    int row0 = blockIdx.x * 128;
    int tn = tid & 15, tm = tid >> 4;

    ull acc[4][2];                        // [row-pair][col of pair {2tn,2tn+1}]
#pragma unroll
    for (int jp = 0; jp < 4; jp++) { acc[jp][0] = 0ull; acc[jp][1] = 0ull; }

    const float4* A4 = (const float4*)g_h2in;
    const float4* W4 = (const float4*)W2;

    for (int k0 = 0; k0 < K; k0 += 16) {
#pragma unroll
        for (int r = 0; r < 2; r++) {
            int f = tid + r * 256;
            int m = f >> 2, kq = f & 3;
            int row = row0 + m;
            float4 v = make_float4(0.f, 0.f, 0.f, 0.f);
            if (row < M) v = A4[(size_t)row * (K / 4) + (k0 >> 2) + kq];
            As[kq * 4 + 0][m] = v.x;
            As[kq * 4 + 1][m] = v.y;
            As[kq * 4 + 2][m] = v.z;
            As[kq * 4 + 3][m] = v.w;
        }
        if (tid < 128) {
            int k = tid >> 3, nq = tid & 7;
            float4 v = W4[(size_t)(k0 + k) * (N / 4) + nq];
            *(float4*)&Bs[k][nq * 4] = v;
        }
        __syncthreads();
#pragma unroll
        for (int k = 0; k < 16; k++) {
            ulonglong2 a0 = *(const ulonglong2*)&As[k][tm * 8];
            ulonglong2 a1 = *(const ulonglong2*)&As[k][tm * 8 + 4];
            float2 b = *(const float2*)&Bs[k][2 * tn];
            ull b0, b1v;
            DUP2(b0, b.x); DUP2(b1v, b.y);
            ull ap[4] = {a0.x, a0.y, a1.x, a1.y};
#pragma unroll
            for (int jp = 0; jp < 4; jp++) {
                FMA2(acc[jp][0], ap[jp], b0);
                FMA2(acc[jp][1], ap[jp], b1v);
            }
        }
        __syncthreads();
    }

    float s0 = a_src[2 * tn], s1 = a_src[2 * tn + 1];
    float d0 = a_dst[2 * tn], d1 = a_dst[2 * tn + 1];
#pragma unroll
    for (int jp = 0; jp < 4; jp++) {
#pragma unroll
        for (int p = 0; p < 2; p++) {
            int row = row0 + tm * 8 + jp * 2 + p;
            float2 c0 = *(const float2*)&acc[jp][0];
            float2 c1 = *(const float2*)&acc[jp][1];
            float w0 = p ? c0.y : c0.x;
            float w1 = p ? c1.y : c1.x;
            float ps = w0 * s0 + w1 * s1;
            float pd = w0 * d0 + w1 * d1;
#pragma unroll
            for (int o = 8; o >= 1; o >>= 1) {
                ps += __shfl_xor_sync(0xffffffffu, ps, o);
                pd += __shfl_xor_sync(0xffffffffu, pd, o);
            }
            if (row < M) {
                ((float2*)g_h2)[(size_t)row * (NCLS / 2) + tn] = make_float2(w0, w1);
                if (tn == 0) { g_als2[row] = ps; g_ald2[row] = pd; }
            }
        }
    }
}

// ---------------- layer-2 aggregation + log_softmax, warp per node ---------
__global__ void k_agg2(const float* __restrict__ b2, float* __restrict__ out, int M) {
    int w = (blockIdx.x * blockDim.x + threadIdx.x) >> 5;
    int lane = threadIdx.x & 31;
    if (w >= M) return;
    float ald = g_ald2[w];
    int beg = g_off[w], end = g_off[w + 1];
    float s = 0.f, acc = 0.f;
#pragma unroll 2
    for (int idx = beg; idx < end; ++idx) {
        int src = g_csr[idx];
        float e = g_als2[src] + ald;
        e = (e > 0.f) ? e : 0.2f * e;
        float p = __expf(e);
        float hv = g_h2[(size_t)src * NCLS + lane];
        s += p;
        acc += p * hv;
    }
    float v = acc / s + b2[lane];
    float mx = v;
#pragma unroll
    for (int o = 16; o >= 1; o >>= 1) mx = fmaxf(mx, __shfl_xor_sync(0xffffffffu, mx, o));
    float ex = __expf(v - mx);
    float sum = ex;
#pragma unroll
    for (int o = 16; o >= 1; o >>= 1) sum += __shfl_xor_sync(0xffffffffu, sum, o);
    out[(size_t)w * NCLS + lane] = v - mx - logf(sum);
}

// ---------------- launch ----------------------------------------------------
extern "C" void kernel_launch(void* const* d_in, const int* in_sizes, int n_in,
                              void* d_out, int out_size) {
    const float* x   = (const float*)d_in[0];
    const void*  ei  = d_in[1];
    const float* W1  = (const float*)d_in[2];
    const float* as1 = (const float*)d_in[3];
    const float* ad1 = (const float*)d_in[4];
    const float* b1  = (const float*)d_in[5];
    const float* W2  = (const float*)d_in[6];
    const float* as2 = (const float*)d_in[7];
    const float* ad2 = (const float*)d_in[8];
    const float* b2  = (const float*)d_in[9];
    float* out = (float*)d_out;

    int M  = in_sizes[0] / FIN;       // 50000
    int E  = in_sizes[1] / 2;         // 800000
    int Et = E + M;

    // Lazily created on the (uncaptured) correctness call; reused thereafter.
    static cudaStream_t s2 = nullptr;
    static cudaEvent_t eFork = nullptr, eJoin = nullptr;
    if (!s2) {
        cudaStreamCreateWithFlags(&s2, cudaStreamNonBlocking);
        cudaEventCreateWithFlags(&eFork, cudaEventDisableTiming);
        cudaEventCreateWithFlags(&eJoin, cudaEventDisableTiming);
    }

    // Fork: CSR chain on side stream, GEMM1 on main stream, join before agg1.
    cudaEventRecord(eFork, 0);
    cudaStreamWaitEvent(s2, eFork, 0);

    dim3 g1(HIDTOT / 64, (M + 127) / 128);
    k_gemm1<<<g1, 256>>>(x, W1, as1, ad1, M);

    k_zero<<<(M + 255) / 256, 256, 0, s2>>>(M);
    k_convert<<<(Et + 255) / 256, 256, 0, s2>>>(ei, E, M);
    int nb = (M + 1023) / 1024;
    k_scan_local<<<nb, 1024, 0, s2>>>(M);
    k_scan_sums<<<1, 64, 0, s2>>>(nb);
    k_scan_add<<<nb, 1024, 0, s2>>>(M, Et);
    k_scatter<<<(Et + 255) / 256, 256, 0, s2>>>(Et);

    cudaEventRecord(eJoin, s2);
    cudaStreamWaitEvent(0, eJoin, 0);

    k_agg1<<<(M + 7) / 8, 256>>>(b1, M);
    k_gemm2<<<(M + 127) / 128, 256>>>(W2, as2, ad2, M);
    k_agg2<<<(M + 7) / 8, 256>>>(b2, out, M);
}

// round 11
// speedup vs baseline: 1.8759x; 1.2960x over previous
#include <cuda_runtime.h>
#include <cuda_bf16.h>
#include <cstdint>

// Problem constants (fixed shapes per reference)
#define NNODES 50000
#define NEDGES 800000
#define ETOT   (NNODES + NEDGES)
#define FIN    256
#define HIDTOT 256
#define NHEADS 4
#define NCLS   32

typedef unsigned long long ull;

#define FMA2(d, a, b) asm("fma.rn.f32x2 %0, %1, %2, %0;" : "+l"(d) : "l"(a), "l"(b))
#define DUP2(d, s)    asm("mov.b64 %0, {%1, %1};" : "=l"(d) : "f"(s))

__device__ __forceinline__ uint32_t smem_to_u32(const void* p) {
    uint32_t a;
    asm("{ .reg .u64 t; cvta.to.shared.u64 t, %1; cvt.u32.u64 %0, t; }" : "=r"(a) : "l"(p));
    return a;
}

#define LDSM4(r0, r1, r2, r3, addr)                                               \
    asm volatile("ldmatrix.sync.aligned.m8n8.x4.shared.b16 {%0,%1,%2,%3}, [%4];"  \
        : "=r"(r0), "=r"(r1), "=r"(r2), "=r"(r3) : "r"(addr))

#define MMA16816(c0, c1, c2, c3, a0, a1, a2, a3, b0, b1)                          \
    asm volatile("mma.sync.aligned.m16n8k16.row.col.f32.bf16.bf16.f32 "           \
        "{%0,%1,%2,%3}, {%4,%5,%6,%7}, {%8,%9}, {%0,%1,%2,%3};"                   \
        : "+f"(c0), "+f"(c1), "+f"(c2), "+f"(c3)                                  \
        : "r"(a0), "r"(a1), "r"(a2), "r"(a3), "r"(b0), "r"(b1))

// ---------------- scratch ----------------
__device__ int   g_src[ETOT];
__device__ int   g_dst[ETOT];
__device__ int   g_csr[ETOT];
__device__ int   g_count[NNODES];
__device__ int   g_cursor[NNODES];
__device__ int   g_off[NNODES + 1];
__device__ int   g_bsum[64];
__device__ int   g_boff[64];
__device__ float g_h1[(size_t)NNODES * HIDTOT];
__device__ float g_als1[NNODES * NHEADS];
__device__ float g_ald1[NNODES * NHEADS];
__device__ float g_h2in[(size_t)NNODES * HIDTOT];
__device__ float g_h2[(size_t)NNODES * NCLS];
__device__ float g_als2[NNODES];
__device__ float g_ald2[NNODES];

// ---------------- CSR construction ----------------
__global__ void k_zero(int n) {
    int i = blockIdx.x * blockDim.x + threadIdx.x;
    if (i < n) { g_count[i] = 0; g_cursor[i] = 0; }
}

__global__ void k_convert(const void* __restrict__ edges, int E, int n) {
    __shared__ int s_is64;
    if (threadIdx.x == 0) {
        const long long* q = (const long long*)edges;
        int ok = 1;
#pragma unroll
        for (int t = 0; t < 16; t++) {
            long long v = q[t];
            if (v < 0 || v >= (long long)n) ok = 0;
        }
        s_is64 = ok;
    }
    __syncthreads();
    int i = blockIdx.x * blockDim.x + threadIdx.x;
    int Et = E + n;
    if (i >= Et) return;
    int s, d;
    if (i < E) {
        if (s_is64) {
            const long long* q = (const long long*)edges;
            s = (int)q[i]; d = (int)q[(long long)E + i];
        } else {
            const int* q = (const int*)edges;
            s = q[i]; d = q[E + i];
        }
    } else { s = i - E; d = i - E; }
    g_src[i] = s; g_dst[i] = d;
    atomicAdd(&g_count[d], 1);
}

__global__ void k_scan_local(int n) {
    __shared__ int sh[1024];
    int i = blockIdx.x * 1024 + threadIdx.x;
    int v = (i < n) ? g_count[i] : 0;
    sh[threadIdx.x] = v;
    __syncthreads();
    for (int off = 1; off < 1024; off <<= 1) {
        int t = (threadIdx.x >= off) ? sh[threadIdx.x - off] : 0;
        __syncthreads();
        sh[threadIdx.x] += t;
        __syncthreads();
    }
    if (i < n) g_off[i] = sh[threadIdx.x] - v;
    if (threadIdx.x == 1023) g_bsum[blockIdx.x] = sh[1023];
}

__global__ void k_scan_sums(int nb) {
    __shared__ int sh[64];
    int v = (threadIdx.x < nb) ? g_bsum[threadIdx.x] : 0;
    sh[threadIdx.x] = v;
    __syncthreads();
    for (int off = 1; off < 64; off <<= 1) {
        int t = (threadIdx.x >= off) ? sh[threadIdx.x - off] : 0;
        __syncthreads();
        sh[threadIdx.x] += t;
        __syncthreads();
    }
    g_boff[threadIdx.x] = sh[threadIdx.x] - v;
}

__global__ void k_scan_add(int n, int Et) {
    int i = blockIdx.x * 1024 + threadIdx.x;
    if (i < n) g_off[i] += g_boff[blockIdx.x];
    if (i == 0) g_off[n] = Et;
}

__global__ void k_scatter(int Et) {
    int i = blockIdx.x * blockDim.x + threadIdx.x;
    if (i >= Et) return;
    int d = g_dst[i];
    int pos = g_off[d] + atomicAdd(&g_cursor[d], 1);
    g_csr[pos] = g_src[i];
}

// ---------------- GEMM1 via mma.sync bf16 split: h1 = x @ W1 ---------------
// CTA: 128 rows x 128 cols (grid.y selects N half). K chunked by 64.
// Terms: Ahi*Bhi + Ahi*Blo + Alo*Bhi, fp32 accum. 8 warps (4 M x 2 N),
// warp tile 32x64. Fused epilogue: h1 store + per-head a_src/a_dst dots
// (warp's 64 cols == one head).
#define SA_STRIDE 144                   // bytes per row (72 bf16): conflict-free ldmatrix
#define SM_ATT 0                        // 512 floats
#define SM_AHI 2048
#define SM_ALO (SM_AHI + 128 * SA_STRIDE)
#define SM_BHI (SM_ALO + 128 * SA_STRIDE)
#define SM_BLO (SM_BHI + 128 * SA_STRIDE)
#define SM_TOT (SM_BLO + 128 * SA_STRIDE)   // 75776 bytes

__device__ __forceinline__ void pack_hl(const float* f, uint4& h4, uint4& l4) {
    unsigned short hb[8], lb[8];
#pragma unroll
    for (int j = 0; j < 8; j++) {
        __nv_bfloat16 h = __float2bfloat16(f[j]);
        float r = f[j] - __bfloat162float(h);
        __nv_bfloat16 l = __float2bfloat16(r);
        hb[j] = __bfloat16_as_ushort(h);
        lb[j] = __bfloat16_as_ushort(l);
    }
    h4.x = (uint32_t)hb[0] | ((uint32_t)hb[1] << 16);
    h4.y = (uint32_t)hb[2] | ((uint32_t)hb[3] << 16);
    h4.z = (uint32_t)hb[4] | ((uint32_t)hb[5] << 16);
    h4.w = (uint32_t)hb[6] | ((uint32_t)hb[7] << 16);
    l4.x = (uint32_t)lb[0] | ((uint32_t)lb[1] << 16);
    l4.y = (uint32_t)lb[2] | ((uint32_t)lb[3] << 16);
    l4.z = (uint32_t)lb[4] | ((uint32_t)lb[5] << 16);
    l4.w = (uint32_t)lb[6] | ((uint32_t)lb[7] << 16);
}

__global__ void __launch_bounds__(256, 2) k_gemm1_mma(
    const float* __restrict__ X, const float* __restrict__ W,
    const float* __restrict__ a_src, const float* __restrict__ a_dst, int M) {
    extern __shared__ char smem[];
    uint32_t sb = smem_to_u32(smem);
    float* s_att = (float*)(smem + SM_ATT);
    int tid = threadIdx.x;
    int wid = tid >> 5, lane = tid & 31;
    int row0 = blockIdx.x * 128;
    int col0 = blockIdx.y * 128;
    int wm = wid & 3, wn = wid >> 2;    // warp rows: wm*32.., cols: wn*64..

    s_att[tid] = a_src[tid];
    s_att[256 + tid] = a_dst[tid];

    float c[2][8][4];                    // [m16 tile][n8 frag][4]
#pragma unroll
    for (int mt = 0; mt < 2; mt++)
#pragma unroll
        for (int nf = 0; nf < 8; nf++)
#pragma unroll
            for (int q = 0; q < 4; q++) c[mt][nf][q] = 0.f;

    const float4* X4 = (const float4*)X;

    for (int kc = 0; kc < 4; kc++) {
        int k0 = kc * 64;
        __syncthreads();                 // protect smem from previous iter reads
        // ---- A staging: 128 rows x 64 k ----
#pragma unroll
        for (int i = 0; i < 2; i++) {
            int u = tid + 256 * i;       // 512 units: (row, 16-k group)
            int m = u >> 2, kg = u & 3;
            int row = row0 + m;
            float f[16];
            if (row < M) {
#pragma unroll
                for (int q = 0; q < 4; q++) {
                    float4 v = X4[(size_t)row * 64 + (k0 >> 2) + kg * 4 + q];
                    f[q * 4 + 0] = v.x; f[q * 4 + 1] = v.y;
                    f[q * 4 + 2] = v.z; f[q * 4 + 3] = v.w;
                }
            } else {
#pragma unroll
                for (int j = 0; j < 16; j++) f[j] = 0.f;
            }
            uint4 h0, l0, h1, l1;
            pack_hl(f, h0, l0);
            pack_hl(f + 8, h1, l1);
            uint32_t off = (uint32_t)(m * SA_STRIDE + kg * 32);
            *(uint4*)(smem + SM_AHI + off) = h0;
            *(uint4*)(smem + SM_AHI + off + 16) = h1;
            *(uint4*)(smem + SM_ALO + off) = l0;
            *(uint4*)(smem + SM_ALO + off + 16) = l1;
        }
        // ---- B staging (transpose): sB[n][k] = W[k0+k][col0+n] ----
        {
            int n = tid & 127, kh = tid >> 7;  // kh: 0/1, 32 k each
            float f[32];
#pragma unroll
            for (int j = 0; j < 32; j++)
                f[j] = W[(size_t)(k0 + kh * 32 + j) * 256 + col0 + n];
            uint4 h4[4], l4[4];
#pragma unroll
            for (int q = 0; q < 4; q++) pack_hl(f + q * 8, h4[q], l4[q]);
            uint32_t off = (uint32_t)(n * SA_STRIDE + kh * 64);
#pragma unroll
            for (int q = 0; q < 4; q++) {
                *(uint4*)(smem + SM_BHI + off + q * 16) = h4[q];
                *(uint4*)(smem + SM_BLO + off + q * 16) = l4[q];
            }
        }
        __syncthreads();
        // ---- compute: 4 k16 steps x 3 terms ----
#pragma unroll
        for (int kk = 0; kk < 4; kk++) {
            uint32_t aoff = (uint32_t)((wm * 32 + (lane & 15)) * SA_STRIDE
                                       + kk * 32 + (lane >> 4) * 16);
            uint32_t ah[2][4], al[2][4];
            LDSM4(ah[0][0], ah[0][1], ah[0][2], ah[0][3], sb + SM_AHI + aoff);
            LDSM4(ah[1][0], ah[1][1], ah[1][2], ah[1][3],
                  sb + SM_AHI + aoff + 16 * SA_STRIDE);
            LDSM4(al[0][0], al[0][1], al[0][2], al[0][3], sb + SM_ALO + aoff);
            LDSM4(al[1][0], al[1][1], al[1][2], al[1][3],
                  sb + SM_ALO + aoff + 16 * SA_STRIDE);
#pragma unroll
            for (int nt2 = 0; nt2 < 4; nt2++) {   // 16 n-rows per group
                int nrow = wn * 64 + nt2 * 16 + (lane & 7) + ((lane >> 4) << 3);
                uint32_t boff = (uint32_t)(nrow * SA_STRIDE + kk * 32
                                           + ((lane >> 3) & 1) * 16);
                uint32_t bh[4], bl[4];
                LDSM4(bh[0], bh[1], bh[2], bh[3], sb + SM_BHI + boff);
                LDSM4(bl[0], bl[1], bl[2], bl[3], sb + SM_BLO + boff);
#pragma unroll
                for (int half = 0; half < 2; half++) {
                    int nf = nt2 * 2 + half;
#pragma unroll
                    for (int mt = 0; mt < 2; mt++) {
                        MMA16816(c[mt][nf][0], c[mt][nf][1], c[mt][nf][2], c[mt][nf][3],
                                 ah[mt][0], ah[mt][1], ah[mt][2], ah[mt][3],
                                 bh[half * 2], bh[half * 2 + 1]);
                        MMA16816(c[mt][nf][0], c[mt][nf][1], c[mt][nf][2], c[mt][nf][3],
                                 ah[mt][0], ah[mt][1], ah[mt][2], ah[mt][3],
                                 bl[half * 2], bl[half * 2 + 1]);
                        MMA16816(c[mt][nf][0], c[mt][nf][1], c[mt][nf][2], c[mt][nf][3],
                                 al[mt][0], al[mt][1], al[mt][2], al[mt][3],
                                 bh[half * 2], bh[half * 2 + 1]);
                    }
                }
            }
        }
    }

    // ---- epilogue: store h1 + fused per-head attention dots ----
    int head = blockIdx.y * 2 + wn;
    int cbase = col0 + wn * 64;
#pragma unroll
    for (int mt = 0; mt < 2; mt++) {
#pragma unroll
        for (int rh = 0; rh < 2; rh++) {
            int row = row0 + wm * 32 + mt * 16 + rh * 8 + (lane >> 2);
            float ds = 0.f, dd = 0.f;
#pragma unroll
            for (int nf = 0; nf < 8; nf++) {
                int colw = nf * 8 + (lane & 3) * 2;
                float v0 = c[mt][nf][rh * 2];
                float v1 = c[mt][nf][rh * 2 + 1];
                int ca = cbase + colw;
                ds += v0 * s_att[ca] + v1 * s_att[ca + 1];
                dd += v0 * s_att[256 + ca] + v1 * s_att[256 + ca + 1];
                if (row < M)
                    *(float2*)(g_h1 + (size_t)row * 256 + ca) = make_float2(v0, v1);
            }
            ds += __shfl_xor_sync(0xffffffffu, ds, 1);
            ds += __shfl_xor_sync(0xffffffffu, ds, 2);
            dd += __shfl_xor_sync(0xffffffffu, dd, 1);
            dd += __shfl_xor_sync(0xffffffffu, dd, 2);
            if ((lane & 3) == 0 && row < M) {
                g_als1[row * NHEADS + head] = ds;
                g_ald1[row * NHEADS + head] = dd;
            }
        }
    }
}

// ---------------- layer-1 aggregation ----------------
__global__ void k_agg1(const float* __restrict__ b1, int M) {
    int w = (blockIdx.x * blockDim.x + threadIdx.x) >> 5;
    int lane = threadIdx.x & 31;
    if (w >= M) return;
    int h = lane >> 3;
    float ald = g_ald1[w * NHEADS + h];
    int beg = g_off[w], end = g_off[w + 1];
    float s = 0.f;
    float acc[8];
#pragma unroll
    for (int j = 0; j < 8; j++) acc[j] = 0.f;
#pragma unroll 2
    for (int idx = beg; idx < end; ++idx) {
        int src = g_csr[idx];
        float e = g_als1[src * NHEADS + h] + ald;
        e = (e > 0.f) ? e : 0.2f * e;
        float p = __expf(e);
        const float4* hp = (const float4*)(g_h1 + (size_t)src * HIDTOT);
        float4 v0 = hp[lane * 2], v1 = hp[lane * 2 + 1];
        s += p;
        acc[0] += p * v0.x; acc[1] += p * v0.y;
        acc[2] += p * v0.z; acc[3] += p * v0.w;
        acc[4] += p * v1.x; acc[5] += p * v1.y;
        acc[6] += p * v1.z; acc[7] += p * v1.w;
    }
    float inv = 1.f / s;
#pragma unroll
    for (int j = 0; j < 8; j++) {
        float v = acc[j] * inv + b1[lane * 8 + j];
        v = (v > 0.f) ? v : (__expf(v) - 1.f);
        g_h2in[(size_t)w * HIDTOT + lane * 8 + j] = v;
    }
}

// ---------------- GEMM2 (FFMA2) + fused al2 ----------------
__global__ void k_gemm2(const float* __restrict__ W2,
                        const float* __restrict__ a_src, const float* __restrict__ a_dst,
                        int M) {
    const int K = HIDTOT, N = NCLS;
    __shared__ float As[16][132];
    __shared__ float Bs[16][36];
    int tid = threadIdx.x;
    int row0 = blockIdx.x * 128;
    int tn = tid & 15, tm = tid >> 4;

    ull acc[4][2];
#pragma unroll
    for (int jp = 0; jp < 4; jp++) { acc[jp][0] = 0ull; acc[jp][1] = 0ull; }

    const float4* A4 = (const float4*)g_h2in;
    const float4* W4 = (const float4*)W2;

    for (int k0 = 0; k0 < K; k0 += 16) {
#pragma unroll
        for (int r = 0; r < 2; r++) {
            int f = tid + r * 256;
            int m = f >> 2, kq = f & 3;
            int row = row0 + m;
            float4 v = make_float4(0.f, 0.f, 0.f, 0.f);
            if (row < M) v = A4[(size_t)row * (K / 4) + (k0 >> 2) + kq];
            As[kq * 4 + 0][m] = v.x;
            As[kq * 4 + 1][m] = v.y;
            As[kq * 4 + 2][m] = v.z;
            As[kq * 4 + 3][m] = v.w;
        }
        if (tid < 128) {
            int k = tid >> 3, nq = tid & 7;
            float4 v = W4[(size_t)(k0 + k) * (N / 4) + nq];
            *(float4*)&Bs[k][nq * 4] = v;
        }
        __syncthreads();
#pragma unroll
        for (int k = 0; k < 16; k++) {
            ulonglong2 a0 = *(const ulonglong2*)&As[k][tm * 8];
            ulonglong2 a1 = *(const ulonglong2*)&As[k][tm * 8 + 4];
            float2 b = *(const float2*)&Bs[k][2 * tn];
            ull b0, b1v;
            DUP2(b0, b.x); DUP2(b1v, b.y);
            ull ap[4] = {a0.x, a0.y, a1.x, a1.y};
#pragma unroll
            for (int jp = 0; jp < 4; jp++) {
                FMA2(acc[jp][0], ap[jp], b0);
                FMA2(acc[jp][1], ap[jp], b1v);
            }
        }
        __syncthreads();
    }

    float s0 = a_src[2 * tn], s1 = a_src[2 * tn + 1];
    float d0 = a_dst[2 * tn], d1 = a_dst[2 * tn + 1];
#pragma unroll
    for (int jp = 0; jp < 4; jp++) {
#pragma unroll
        for (int p = 0; p < 2; p++) {
            int row = row0 + tm * 8 + jp * 2 + p;
            float2 c0 = *(const float2*)&acc[jp][0];
            float2 c1 = *(const float2*)&acc[jp][1];
            float w0 = p ? c0.y : c0.x;
            float w1 = p ? c1.y : c1.x;
            float ps = w0 * s0 + w1 * s1;
            float pd = w0 * d0 + w1 * d1;
#pragma unroll
            for (int o = 8; o >= 1; o >>= 1) {
                ps += __shfl_xor_sync(0xffffffffu, ps, o);
                pd += __shfl_xor_sync(0xffffffffu, pd, o);
            }
            if (row < M) {
                ((float2*)g_h2)[(size_t)row * (NCLS / 2) + tn] = make_float2(w0, w1);
                if (tn == 0) { g_als2[row] = ps; g_ald2[row] = pd; }
            }
        }
    }
}

// ---------------- layer-2 aggregation + log_softmax ----------------
__global__ void k_agg2(const float* __restrict__ b2, float* __restrict__ out, int M) {
    int w = (blockIdx.x * blockDim.x + threadIdx.x) >> 5;
    int lane = threadIdx.x & 31;
    if (w >= M) return;
    float ald = g_ald2[w];
    int beg = g_off[w], end = g_off[w + 1];
    float s = 0.f, acc = 0.f;
#pragma unroll 2
    for (int idx = beg; idx < end; ++idx) {
        int src = g_csr[idx];
        float e = g_als2[src] + ald;
        e = (e > 0.f) ? e : 0.2f * e;
        float p = __expf(e);
        float hv = g_h2[(size_t)src * NCLS + lane];
        s += p;
        acc += p * hv;
    }
    float v = acc / s + b2[lane];
    float mx = v;
#pragma unroll
    for (int o = 16; o >= 1; o >>= 1) mx = fmaxf(mx, __shfl_xor_sync(0xffffffffu, mx, o));
    float ex = __expf(v - mx);
    float sum = ex;
#pragma unroll
    for (int o = 16; o >= 1; o >>= 1) sum += __shfl_xor_sync(0xffffffffu, sum, o);
    out[(size_t)w * NCLS + lane] = v - mx - logf(sum);
}

// ---------------- launch ----------------
extern "C" void kernel_launch(void* const* d_in, const int* in_sizes, int n_in,
                              void* d_out, int out_size) {
    const float* x   = (const float*)d_in[0];
    const void*  ei  = d_in[1];
    const float* W1  = (const float*)d_in[2];
    const float* as1 = (const float*)d_in[3];
    const float* ad1 = (const float*)d_in[4];
    const float* b1  = (const float*)d_in[5];
    const float* W2  = (const float*)d_in[6];
    const float* as2 = (const float*)d_in[7];
    const float* ad2 = (const float*)d_in[8];
    const float* b2  = (const float*)d_in[9];
    float* out = (float*)d_out;

    int M  = in_sizes[0] / FIN;
    int E  = in_sizes[1] / 2;
    int Et = E + M;

    static cudaStream_t s2 = nullptr;
    static cudaEvent_t eFork = nullptr, eJoin = nullptr;
    if (!s2) {
        cudaStreamCreateWithFlags(&s2, cudaStreamNonBlocking);
        cudaEventCreateWithFlags(&eFork, cudaEventDisableTiming);
        cudaEventCreateWithFlags(&eJoin, cudaEventDisableTiming);
        cudaFuncSetAttribute(k_gemm1_mma, cudaFuncAttributeMaxDynamicSharedMemorySize, SM_TOT);
    }

    cudaEventRecord(eFork, 0);
    cudaStreamWaitEvent(s2, eFork, 0);

    dim3 g1((M + 127) / 128, 2);
    k_gemm1_mma<<<g1, 256, SM_TOT>>>(x, W1, as1, ad1, M);

    k_zero<<<(M + 255) / 256, 256, 0, s2>>>(M);
    k_convert<<<(Et + 255) / 256, 256, 0, s2>>>(ei, E, M);
    int nb = (M + 1023) / 1024;
    k_scan_local<<<nb, 1024, 0, s2>>>(M);
    k_scan_sums<<<1, 64, 0, s2>>>(nb);
    k_scan_add<<<nb, 1024, 0, s2>>>(M, Et);
    k_scatter<<<(Et + 255) / 256, 256, 0, s2>>>(Et);

    cudaEventRecord(eJoin, s2);
    cudaStreamWaitEvent(0, eJoin, 0);

    k_agg1<<<(M + 7) / 8, 256>>>(b1, M);
    k_gemm2<<<(M + 127) / 128, 256>>>(W2, as2, ad2, M);
    k_agg2<<<(M + 7) / 8, 256>>>(b2, out, M);
}

// round 12
// speedup vs baseline: 2.1641x; 1.1536x over previous
#include <cuda_runtime.h>
#include <cuda_bf16.h>
#include <cuda_fp16.h>
#include <cstdint>

// Problem constants (fixed shapes per reference)
#define NNODES 50000
#define NEDGES 800000
#define ETOT   (NNODES + NEDGES)
#define FIN    256
#define HIDTOT 256
#define NHEADS 4
#define NCLS   32

typedef unsigned long long ull;

#define FMA2(d, a, b) asm("fma.rn.f32x2 %0, %1, %2, %0;" : "+l"(d) : "l"(a), "l"(b))
#define DUP2(d, s)    asm("mov.b64 %0, {%1, %1};" : "=l"(d) : "f"(s))

__device__ __forceinline__ uint32_t smem_to_u32(const void* p) {
    uint32_t a;
    asm("{ .reg .u64 t; cvta.to.shared.u64 t, %1; cvt.u32.u64 %0, t; }" : "=r"(a) : "l"(p));
    return a;
}

#define LDSM4(r0, r1, r2, r3, addr)                                               \
    asm volatile("ldmatrix.sync.aligned.m8n8.x4.shared.b16 {%0,%1,%2,%3}, [%4];"  \
        : "=r"(r0), "=r"(r1), "=r"(r2), "=r"(r3) : "r"(addr))

#define MMA16816(c0, c1, c2, c3, a0, a1, a2, a3, b0, b1)                          \
    asm volatile("mma.sync.aligned.m16n8k16.row.col.f32.bf16.bf16.f32 "           \
        "{%0,%1,%2,%3}, {%4,%5,%6,%7}, {%8,%9}, {%0,%1,%2,%3};"                   \
        : "+f"(c0), "+f"(c1), "+f"(c2), "+f"(c3)                                  \
        : "r"(a0), "r"(a1), "r"(a2), "r"(a3), "r"(b0), "r"(b1))

// ---------------- scratch ----------------
__device__ int    g_src[ETOT];
__device__ int    g_dst[ETOT];
__device__ int    g_csr[ETOT];
__device__ int    g_count[NNODES];
__device__ int    g_cursor[NNODES];
__device__ int    g_off[NNODES + 1];
__device__ int    g_bsum[64];
__device__ int    g_boff[64];
__device__ __half g_h1h[(size_t)NNODES * HIDTOT];     // fp16 h1 (gather-only)
__device__ float  g_als1[NNODES * NHEADS];
__device__ float  g_ald1[NNODES * NHEADS];
__device__ float  g_h2in[(size_t)NNODES * HIDTOT];
__device__ __half g_h2h[(size_t)NNODES * NCLS];       // fp16 h2 (gather-only)
__device__ float  g_als2[NNODES];
__device__ float  g_ald2[NNODES];

// ---------------- CSR construction ----------------
__global__ void k_zero(int n) {
    int i = blockIdx.x * blockDim.x + threadIdx.x;
    if (i < n) { g_count[i] = 0; g_cursor[i] = 0; }
}

__global__ void k_convert(const void* __restrict__ edges, int E, int n) {
    __shared__ int s_is64;
    if (threadIdx.x == 0) {
        const long long* q = (const long long*)edges;
        int ok = 1;
#pragma unroll
        for (int t = 0; t < 16; t++) {
            long long v = q[t];
            if (v < 0 || v >= (long long)n) ok = 0;
        }
        s_is64 = ok;
    }
    __syncthreads();
    int i = blockIdx.x * blockDim.x + threadIdx.x;
    int Et = E + n;
    if (i >= Et) return;
    int s, d;
    if (i < E) {
        if (s_is64) {
            const long long* q = (const long long*)edges;
            s = (int)q[i]; d = (int)q[(long long)E + i];
        } else {
            const int* q = (const int*)edges;
            s = q[i]; d = q[E + i];
        }
    } else { s = i - E; d = i - E; }
    g_src[i] = s; g_dst[i] = d;
    atomicAdd(&g_count[d], 1);
}

__global__ void k_scan_local(int n) {
    __shared__ int sh[1024];
    int i = blockIdx.x * 1024 + threadIdx.x;
    int v = (i < n) ? g_count[i] : 0;
    sh[threadIdx.x] = v;
    __syncthreads();
    for (int off = 1; off < 1024; off <<= 1) {
        int t = (threadIdx.x >= off) ? sh[threadIdx.x - off] : 0;
        __syncthreads();
        sh[threadIdx.x] += t;
        __syncthreads();
    }
    if (i < n) g_off[i] = sh[threadIdx.x] - v;
    if (threadIdx.x == 1023) g_bsum[blockIdx.x] = sh[1023];
}

__global__ void k_scan_sums(int nb) {
    __shared__ int sh[64];
    int v = (threadIdx.x < nb) ? g_bsum[threadIdx.x] : 0;
    sh[threadIdx.x] = v;
    __syncthreads();
    for (int off = 1; off < 64; off <<= 1) {
        int t = (threadIdx.x >= off) ? sh[threadIdx.x - off] : 0;
        __syncthreads();
        sh[threadIdx.x] += t;
        __syncthreads();
    }
    g_boff[threadIdx.x] = sh[threadIdx.x] - v;
}

__global__ void k_scan_add(int n, int Et) {
    int i = blockIdx.x * 1024 + threadIdx.x;
    if (i < n) g_off[i] += g_boff[blockIdx.x];
    if (i == 0) g_off[n] = Et;
}

__global__ void k_scatter(int Et) {
    int i = blockIdx.x * blockDim.x + threadIdx.x;
    if (i >= Et) return;
    int d = g_dst[i];
    int pos = g_off[d] + atomicAdd(&g_cursor[d], 1);
    g_csr[pos] = g_src[i];
}

// ---------------- GEMM1 via mma.sync bf16 split: h1 = x @ W1 ---------------
// CTA: 128 rows x 128 cols (grid.y selects N half). K chunked by 64.
// Terms: Ahi*Bhi + Ahi*Blo + Alo*Bhi, fp32 accum. 8 warps (4 M x 2 N),
// warp tile 32x64. Fused epilogue: fp16 h1 store + per-head a_src/a_dst dots.
#define SA_STRIDE 144
#define SM_ATT 0
#define SM_AHI 2048
#define SM_ALO (SM_AHI + 128 * SA_STRIDE)
#define SM_BHI (SM_ALO + 128 * SA_STRIDE)
#define SM_BLO (SM_BHI + 128 * SA_STRIDE)
#define SM_TOT (SM_BLO + 128 * SA_STRIDE)   // 75776 bytes

__device__ __forceinline__ void pack_hl(const float* f, uint4& h4, uint4& l4) {
    unsigned short hb[8], lb[8];
#pragma unroll
    for (int j = 0; j < 8; j++) {
        __nv_bfloat16 h = __float2bfloat16(f[j]);
        float r = f[j] - __bfloat162float(h);
        __nv_bfloat16 l = __float2bfloat16(r);
        hb[j] = __bfloat16_as_ushort(h);
        lb[j] = __bfloat16_as_ushort(l);
    }
    h4.x = (uint32_t)hb[0] | ((uint32_t)hb[1] << 16);
    h4.y = (uint32_t)hb[2] | ((uint32_t)hb[3] << 16);
    h4.z = (uint32_t)hb[4] | ((uint32_t)hb[5] << 16);
    h4.w = (uint32_t)hb[6] | ((uint32_t)hb[7] << 16);
    l4.x = (uint32_t)lb[0] | ((uint32_t)lb[1] << 16);
    l4.y = (uint32_t)lb[2] | ((uint32_t)lb[3] << 16);
    l4.z = (uint32_t)lb[4] | ((uint32_t)lb[5] << 16);
    l4.w = (uint32_t)lb[6] | ((uint32_t)lb[7] << 16);
}

__global__ void __launch_bounds__(256, 2) k_gemm1_mma(
    const float* __restrict__ X, const float* __restrict__ W,
    const float* __restrict__ a_src, const float* __restrict__ a_dst, int M) {
    extern __shared__ char smem[];
    uint32_t sb = smem_to_u32(smem);
    float* s_att = (float*)(smem + SM_ATT);
    int tid = threadIdx.x;
    int wid = tid >> 5, lane = tid & 31;
    int row0 = blockIdx.x * 128;
    int col0 = blockIdx.y * 128;
    int wm = wid & 3, wn = wid >> 2;

    s_att[tid] = a_src[tid];
    s_att[256 + tid] = a_dst[tid];

    float c[2][8][4];
#pragma unroll
    for (int mt = 0; mt < 2; mt++)
#pragma unroll
        for (int nf = 0; nf < 8; nf++)
#pragma unroll
            for (int q = 0; q < 4; q++) c[mt][nf][q] = 0.f;

    const float4* X4 = (const float4*)X;

    for (int kc = 0; kc < 4; kc++) {
        int k0 = kc * 64;
        __syncthreads();
        // ---- A staging: 128 rows x 64 k ----
#pragma unroll
        for (int i = 0; i < 2; i++) {
            int u = tid + 256 * i;
            int m = u >> 2, kg = u & 3;
            int row = row0 + m;
            float f[16];
            if (row < M) {
#pragma unroll
                for (int q = 0; q < 4; q++) {
                    float4 v = X4[(size_t)row * 64 + (k0 >> 2) + kg * 4 + q];
                    f[q * 4 + 0] = v.x; f[q * 4 + 1] = v.y;
                    f[q * 4 + 2] = v.z; f[q * 4 + 3] = v.w;
                }
            } else {
#pragma unroll
                for (int j = 0; j < 16; j++) f[j] = 0.f;
            }
            uint4 h0, l0, h1, l1;
            pack_hl(f, h0, l0);
            pack_hl(f + 8, h1, l1);
            uint32_t off = (uint32_t)(m * SA_STRIDE + kg * 32);
            *(uint4*)(smem + SM_AHI + off) = h0;
            *(uint4*)(smem + SM_AHI + off + 16) = h1;
            *(uint4*)(smem + SM_ALO + off) = l0;
            *(uint4*)(smem + SM_ALO + off + 16) = l1;
        }
        // ---- B staging (transpose): sB[n][k] = W[k0+k][col0+n] ----
        {
            int n = tid & 127, kh = tid >> 7;
            float f[32];
#pragma unroll
            for (int j = 0; j < 32; j++)
                f[j] = W[(size_t)(k0 + kh * 32 + j) * 256 + col0 + n];
            uint4 h4[4], l4[4];
#pragma unroll
            for (int q = 0; q < 4; q++) pack_hl(f + q * 8, h4[q], l4[q]);
            uint32_t off = (uint32_t)(n * SA_STRIDE + kh * 64);
#pragma unroll
            for (int q = 0; q < 4; q++) {
                *(uint4*)(smem + SM_BHI + off + q * 16) = h4[q];
                *(uint4*)(smem + SM_BLO + off + q * 16) = l4[q];
            }
        }
        __syncthreads();
#pragma unroll
        for (int kk = 0; kk < 4; kk++) {
            uint32_t aoff = (uint32_t)((wm * 32 + (lane & 15)) * SA_STRIDE
                                       + kk * 32 + (lane >> 4) * 16);
            uint32_t ah[2][4], al[2][4];
            LDSM4(ah[0][0], ah[0][1], ah[0][2], ah[0][3], sb + SM_AHI + aoff);
            LDSM4(ah[1][0], ah[1][1], ah[1][2], ah[1][3],
                  sb + SM_AHI + aoff + 16 * SA_STRIDE);
            LDSM4(al[0][0], al[0][1], al[0][2], al[0][3], sb + SM_ALO + aoff);
            LDSM4(al[1][0], al[1][1], al[1][2], al[1][3],
                  sb + SM_ALO + aoff + 16 * SA_STRIDE);
#pragma unroll
            for (int nt2 = 0; nt2 < 4; nt2++) {
                int nrow = wn * 64 + nt2 * 16 + (lane & 7) + ((lane >> 4) << 3);
                uint32_t boff = (uint32_t)(nrow * SA_STRIDE + kk * 32
                                           + ((lane >> 3) & 1) * 16);
                uint32_t bh[4], bl[4];
                LDSM4(bh[0], bh[1], bh[2], bh[3], sb + SM_BHI + boff);
                LDSM4(bl[0], bl[1], bl[2], bl[3], sb + SM_BLO + boff);
#pragma unroll
                for (int half = 0; half < 2; half++) {
                    int nf = nt2 * 2 + half;
#pragma unroll
                    for (int mt = 0; mt < 2; mt++) {
                        MMA16816(c[mt][nf][0], c[mt][nf][1], c[mt][nf][2], c[mt][nf][3],
                                 ah[mt][0], ah[mt][1], ah[mt][2], ah[mt][3],
                                 bh[half * 2], bh[half * 2 + 1]);
                        MMA16816(c[mt][nf][0], c[mt][nf][1], c[mt][nf][2], c[mt][nf][3],
                                 ah[mt][0], ah[mt][1], ah[mt][2], ah[mt][3],
                                 bl[half * 2], bl[half * 2 + 1]);
                        MMA16816(c[mt][nf][0], c[mt][nf][1], c[mt][nf][2], c[mt][nf][3],
                                 al[mt][0], al[mt][1], al[mt][2], al[mt][3],
                                 bh[half * 2], bh[half * 2 + 1]);
                    }
                }
            }
        }
    }

    // ---- epilogue: store h1 (fp16) + fused per-head attention dots ----
    int head = blockIdx.y * 2 + wn;
    int cbase = col0 + wn * 64;
#pragma unroll
    for (int mt = 0; mt < 2; mt++) {
#pragma unroll
        for (int rh = 0; rh < 2; rh++) {
            int row = row0 + wm * 32 + mt * 16 + rh * 8 + (lane >> 2);
            float ds = 0.f, dd = 0.f;
#pragma unroll
            for (int nf = 0; nf < 8; nf++) {
                int colw = nf * 8 + (lane & 3) * 2;
                float v0 = c[mt][nf][rh * 2];
                float v1 = c[mt][nf][rh * 2 + 1];
                int ca = cbase + colw;
                ds += v0 * s_att[ca] + v1 * s_att[ca + 1];
                dd += v0 * s_att[256 + ca] + v1 * s_att[256 + ca + 1];
                if (row < M)
                    *(__half2*)(g_h1h + (size_t)row * 256 + ca) =
                        __floats2half2_rn(v0, v1);
            }
            ds += __shfl_xor_sync(0xffffffffu, ds, 1);
            ds += __shfl_xor_sync(0xffffffffu, ds, 2);
            dd += __shfl_xor_sync(0xffffffffu, dd, 1);
            dd += __shfl_xor_sync(0xffffffffu, dd, 2);
            if ((lane & 3) == 0 && row < M) {
                g_als1[row * NHEADS + head] = ds;
                g_ald1[row * NHEADS + head] = dd;
            }
        }
    }
}

// ---------------- layer-1 aggregation: fp16 gather, fp32 accum -------------
__global__ void k_agg1(const float* __restrict__ b1, int M) {
    int w = (blockIdx.x * blockDim.x + threadIdx.x) >> 5;
    int lane = threadIdx.x & 31;
    if (w >= M) return;
    int h = lane >> 3;
    float ald = g_ald1[w * NHEADS + h];
    int beg = g_off[w], end = g_off[w + 1];
    float s = 0.f;
    float acc[8];
#pragma unroll
    for (int j = 0; j < 8; j++) acc[j] = 0.f;
#pragma unroll 2
    for (int idx = beg; idx < end; ++idx) {
        int src = g_csr[idx];
        float e = g_als1[src * NHEADS + h] + ald;
        e = (e > 0.f) ? e : 0.2f * e;
        float p = __expf(e);
        uint4 u = *(const uint4*)(g_h1h + (size_t)src * HIDTOT + lane * 8);
        float2 f0 = __half22float2(*(const __half2*)&u.x);
        float2 f1 = __half22float2(*(const __half2*)&u.y);
        float2 f2 = __half22float2(*(const __half2*)&u.z);
        float2 f3 = __half22float2(*(const __half2*)&u.w);
        s += p;
        acc[0] += p * f0.x; acc[1] += p * f0.y;
        acc[2] += p * f1.x; acc[3] += p * f1.y;
        acc[4] += p * f2.x; acc[5] += p * f2.y;
        acc[6] += p * f3.x; acc[7] += p * f3.y;
    }
    float inv = 1.f / s;
#pragma unroll
    for (int j = 0; j < 8; j++) {
        float v = acc[j] * inv + b1[lane * 8 + j];
        v = (v > 0.f) ? v : (__expf(v) - 1.f);
        g_h2in[(size_t)w * HIDTOT + lane * 8 + j] = v;
    }
}

// ---------------- GEMM2 (FFMA2) + fused al2, fp16 h2 store -----------------
__global__ void k_gemm2(const float* __restrict__ W2,
                        const float* __restrict__ a_src, const float* __restrict__ a_dst,
                        int M) {
    const int K = HIDTOT, N = NCLS;
    __shared__ float As[16][132];
    __shared__ float Bs[16][36];
    int tid = threadIdx.x;
    int row0 = blockIdx.x * 128;
    int tn = tid & 15, tm = tid >> 4;

    ull acc[4][2];
#pragma unroll
    for (int jp = 0; jp < 4; jp++) { acc[jp][0] = 0ull; acc[jp][1] = 0ull; }

    const float4* A4 = (const float4*)g_h2in;
    const float4* W4 = (const float4*)W2;

    for (int k0 = 0; k0 < K; k0 += 16) {
#pragma unroll
        for (int r = 0; r < 2; r++) {
            int f = tid + r * 256;
            int m = f >> 2, kq = f & 3;
            int row = row0 + m;
            float4 v = make_float4(0.f, 0.f, 0.f, 0.f);
            if (row < M) v = A4[(size_t)row * (K / 4) + (k0 >> 2) + kq];
            As[kq * 4 + 0][m] = v.x;
            As[kq * 4 + 1][m] = v.y;
            As[kq * 4 + 2][m] = v.z;
            As[kq * 4 + 3][m] = v.w;
        }
        if (tid < 128) {
            int k = tid >> 3, nq = tid & 7;
            float4 v = W4[(size_t)(k0 + k) * (N / 4) + nq];
            *(float4*)&Bs[k][nq * 4] = v;
        }
        __syncthreads();
#pragma unroll
        for (int k = 0; k < 16; k++) {
            ulonglong2 a0 = *(const ulonglong2*)&As[k][tm * 8];
            ulonglong2 a1 = *(const ulonglong2*)&As[k][tm * 8 + 4];
            float2 b = *(const float2*)&Bs[k][2 * tn];
            ull b0, b1v;
            DUP2(b0, b.x); DUP2(b1v, b.y);
            ull ap[4] = {a0.x, a0.y, a1.x, a1.y};
#pragma unroll
            for (int jp = 0; jp < 4; jp++) {
                FMA2(acc[jp][0], ap[jp], b0);
                FMA2(acc[jp][1], ap[jp], b1v);
            }
        }
        __syncthreads();
    }

    float s0 = a_src[2 * tn], s1 = a_src[2 * tn + 1];
    float d0 = a_dst[2 * tn], d1 = a_dst[2 * tn + 1];
#pragma unroll
    for (int jp = 0; jp < 4; jp++) {
#pragma unroll
        for (int p = 0; p < 2; p++) {
            int row = row0 + tm * 8 + jp * 2 + p;
            float2 c0 = *(const float2*)&acc[jp][0];
            float2 c1 = *(const float2*)&acc[jp][1];
            float w0 = p ? c0.y : c0.x;
            float w1 = p ? c1.y : c1.x;
            float ps = w0 * s0 + w1 * s1;
            float pd = w0 * d0 + w1 * d1;
#pragma unroll
            for (int o = 8; o >= 1; o >>= 1) {
                ps += __shfl_xor_sync(0xffffffffu, ps, o);
                pd += __shfl_xor_sync(0xffffffffu, pd, o);
            }
            if (row < M) {
                *(__half2*)(g_h2h + (size_t)row * NCLS + 2 * tn) =
                    __floats2half2_rn(w0, w1);
                if (tn == 0) { g_als2[row] = ps; g_ald2[row] = pd; }
            }
        }
    }
}

// ---------------- layer-2 aggregation + log_softmax ----------------
__global__ void k_agg2(const float* __restrict__ b2, float* __restrict__ out, int M) {
    int w = (blockIdx.x * blockDim.x + threadIdx.x) >> 5;
    int lane = threadIdx.x & 31;
    if (w >= M) return;
    float ald = g_ald2[w];
    int beg = g_off[w], end = g_off[w + 1];
    float s = 0.f, acc = 0.f;
#pragma unroll 2
    for (int idx = beg; idx < end; ++idx) {
        int src = g_csr[idx];
        float e = g_als2[src] + ald;
        e = (e > 0.f) ? e : 0.2f * e;
        float p = __expf(e);
        float hv = __half2float(g_h2h[(size_t)src * NCLS + lane]);
        s += p;
        acc += p * hv;
    }
    float v = acc / s + b2[lane];
    float mx = v;
#pragma unroll
    for (int o = 16; o >= 1; o >>= 1) mx = fmaxf(mx, __shfl_xor_sync(0xffffffffu, mx, o));
    float ex = __expf(v - mx);
    float sum = ex;
#pragma unroll
    for (int o = 16; o >= 1; o >>= 1) sum += __shfl_xor_sync(0xffffffffu, sum, o);
    out[(size_t)w * NCLS + lane] = v - mx - logf(sum);
}

// ---------------- launch ----------------
extern "C" void kernel_launch(void* const* d_in, const int* in_sizes, int n_in,
                              void* d_out, int out_size) {
    const float* x   = (const float*)d_in[0];
    const void*  ei  = d_in[1];
    const float* W1  = (const float*)d_in[2];
    const float* as1 = (const float*)d_in[3];
    const float* ad1 = (const float*)d_in[4];
    const float* b1  = (const float*)d_in[5];
    const float* W2  = (const float*)d_in[6];
    const float* as2 = (const float*)d_in[7];
    const float* ad2 = (const float*)d_in[8];
    const float* b2  = (const float*)d_in[9];
    float* out = (float*)d_out;

    int M  = in_sizes[0] / FIN;
    int E  = in_sizes[1] / 2;
    int Et = E + M;

    static cudaStream_t s2 = nullptr;
    static cudaEvent_t eFork = nullptr, eJoin = nullptr;
    if (!s2) {
        cudaStreamCreateWithFlags(&s2, cudaStreamNonBlocking);
        cudaEventCreateWithFlags(&eFork, cudaEventDisableTiming);
        cudaEventCreateWithFlags(&eJoin, cudaEventDisableTiming);
        cudaFuncSetAttribute(k_gemm1_mma, cudaFuncAttributeMaxDynamicSharedMemorySize, SM_TOT);
    }

    cudaEventRecord(eFork, 0);
    cudaStreamWaitEvent(s2, eFork, 0);

    dim3 g1((M + 127) / 128, 2);
    k_gemm1_mma<<<g1, 256, SM_TOT>>>(x, W1, as1, ad1, M);

    k_zero<<<(M + 255) / 256, 256, 0, s2>>>(M);
    k_convert<<<(Et + 255) / 256, 256, 0, s2>>>(ei, E, M);
    int nb = (M + 1023) / 1024;
    k_scan_local<<<nb, 1024, 0, s2>>>(M);
    k_scan_sums<<<1, 64, 0, s2>>>(nb);
    k_scan_add<<<nb, 1024, 0, s2>>>(M, Et);
    k_scatter<<<(Et + 255) / 256, 256, 0, s2>>>(Et);

    cudaEventRecord(eJoin, s2);
    cudaStreamWaitEvent(0, eJoin, 0);

    k_agg1<<<(M + 7) / 8, 256>>>(b1, M);
    k_gemm2<<<(M + 127) / 128, 256>>>(W2, as2, ad2, M);
    k_agg2<<<(M + 7) / 8, 256>>>(b2, out, M);
}